// round 10
// baseline (speedup 1.0000x reference)
#include <cuda_runtime.h>
#include <cuda_fp16.h>
#include <cstdint>
#include <math.h>

// ============================================================================
// DUQ head via HMMA 3xFP16-split GEMM, fused feature-split (no prep_feat).
// out[b,c,p] = exp(-3.125 * sum_e (emb[p, c*16+e] - cent[c*16+e])^2)
// emb = feat[b,:,p].w[n,:], n=c*16+e, K=512.
// a = ah+al, b = bh+bl (exact fp16 splits); acc += ah*bh + ah*bl + al*bh (f32).
// A path: cp.async raw fp32 feature tiles ([k][p], coalesced, NO transpose
// kernel) -> in-kernel convert to hi/lo halves in k-major smem ->
// ldmatrix.x4.trans for A fragments.
// CTA tile 128x128, warp tile 32x64 (8 warps/256 thr), BK=32, 2 CTAs/SM.
// Rings: raw A x2 (32KB), half A x2 (32KB), B x3 (48KB). 112.5KB smem.
// ============================================================================

#define BM 128
#define BN 128
#define BK 32
#define KTILES 16              // 512 / 32
#define RAW_OFF  0             // 2 x 16384  (raw fp32 A: 32 k-rows x 512B)
#define HALF_OFF 32768         // 2 x 16384  (half A: hi 8K + lo 8K, k-major 256B rows)
#define B_OFF    65536         // 3 x 16384  (B: hi 8K + lo 8K, n-major 64B rows)
#define CENT_OFF 114688
#define SMEM_TOTAL (114688 + 512)

// -------- device-global scratch (no cudaMalloc allowed) ----------------------
__device__ __half g_bh[524288];     // [1024 n][512 k], n = c*16+e
__device__ __half g_bl[524288];
__device__ float  g_cent[1024];

// -------- helpers -------------------------------------------------------------
__device__ __forceinline__ uint32_t smem_u32(const void* p) {
    uint32_t a;
    asm("{ .reg .u64 t; cvta.to.shared.u64 t, %1; cvt.u32.u64 %0, t; }" : "=r"(a) : "l"(p));
    return a;
}
__device__ __forceinline__ void cp16h(uint32_t dst, const __half* src) {
    asm volatile("cp.async.cg.shared.global [%0], [%1], 16;"
                 :: "r"(dst), "l"(__cvta_generic_to_global(src)));
}
__device__ __forceinline__ void cp16f(uint32_t dst, const float* src) {
    asm volatile("cp.async.cg.shared.global [%0], [%1], 16;"
                 :: "r"(dst), "l"(__cvta_generic_to_global(src)));
}
__device__ __forceinline__ void ldsm4(uint32_t* r, uint32_t addr) {
    asm volatile("ldmatrix.sync.aligned.m8n8.x4.shared.b16 {%0,%1,%2,%3}, [%4];"
                 : "=r"(r[0]), "=r"(r[1]), "=r"(r[2]), "=r"(r[3]) : "r"(addr));
}
__device__ __forceinline__ void ldsm4t(uint32_t* r, uint32_t addr) {
    asm volatile("ldmatrix.sync.aligned.m8n8.x4.trans.shared.b16 {%0,%1,%2,%3}, [%4];"
                 : "=r"(r[0]), "=r"(r[1]), "=r"(r[2]), "=r"(r[3]) : "r"(addr));
}
__device__ __forceinline__ void lds128(float4& v, uint32_t addr) {
    asm volatile("ld.shared.v4.f32 {%0,%1,%2,%3}, [%4];"
                 : "=f"(v.x), "=f"(v.y), "=f"(v.z), "=f"(v.w) : "r"(addr));
}
__device__ __forceinline__ void sts128(uint32_t addr, uint32_t a, uint32_t b,
                                       uint32_t c, uint32_t d) {
    asm volatile("st.shared.v4.b32 [%0], {%1,%2,%3,%4};"
                 :: "r"(addr), "r"(a), "r"(b), "r"(c), "r"(d));
}
__device__ __forceinline__ void mma_f32(float* c, const uint32_t* a, const uint32_t* b) {
    asm volatile("mma.sync.aligned.m16n8k16.row.col.f32.f16.f16.f32 "
                 "{%0,%1,%2,%3}, {%4,%5,%6,%7}, {%8,%9}, {%0,%1,%2,%3};"
                 : "+f"(c[0]), "+f"(c[1]), "+f"(c[2]), "+f"(c[3])
                 : "r"(a[0]), "r"(a[1]), "r"(a[2]), "r"(a[3]), "r"(b[0]), "r"(b[1]));
}

// -------- prep: weights reorder + split, centroids ----------------------------
__global__ void prep_w(const float* __restrict__ wgt, const float* __restrict__ m,
                       const float* __restrict__ Nb) {
    int n = blockIdx.x;                 // n = c*16 + e
    int c = n >> 4, e = n & 15;
    const float* src = wgt + ((size_t)e * 64 + c) * 512;
    for (int k = threadIdx.x; k < 512; k += 128) {
        float v = src[k];
        __half hi = __float2half_rn(v);
        g_bh[(size_t)n * 512 + k] = hi;
        g_bl[(size_t)n * 512 + k] = __float2half_rn(v - __half2float(hi));
    }
    if (threadIdx.x == 0) g_cent[n] = m[e * 64 + c] / Nb[c];
}

// -------- stage fill: raw fp32 A (4 cp) + B halves (4 cp) per thread -----------
__device__ __forceinline__ void fill_stage(uint32_t sb, int kt, const float* feat,
                                           int bb, int pinbase, int n0, int t) {
    int kb = kt * BK;
    // raw A: [k 0..31][p 0..127] fp32, 512B rows, chunk swizzle c ^ (k&7)
    {
        int k = t >> 3, j = t & 7;
        const float* srcrow = feat + ((size_t)(bb * 512 + kb + k)) * 16384 + pinbase;
        uint32_t rbase = sb + RAW_OFF + (uint32_t)((kt & 1) * 16384 + k * 512);
#pragma unroll
        for (int jj = 0; jj < 4; jj++) {
            int c = j * 4 + jj;
            cp16f(rbase + (uint32_t)((c ^ (k & 7)) << 4), srcrow + c * 4);
        }
    }
    // B: [n 0..127][k 0..31] halves, 64B rows, chunk swizzle c ^ ((n>>1)&3)
    {
        int r = t >> 2, cB = t & 3;
#pragma unroll
        for (int i = 0; i < 2; i++) {
            int rr = r + i * 64;
            uint32_t d = sb + B_OFF + (uint32_t)((kt % 3) * 16384 + rr * 64 +
                         ((cB ^ ((rr >> 1) & 3)) << 4));
            size_t bsrc = (size_t)(n0 + rr) * 512 + kb + cB * 8;
            cp16h(d,        g_bh + bsrc);
            cp16h(d + 8192, g_bl + bsrc);
        }
    }
}

// -------- in-kernel fp32 -> (hi,lo) half conversion of one A tile --------------
__device__ __forceinline__ void convert_tile(uint32_t sb, int kt, int t) {
    int k = t >> 3, pg = t & 7;
    uint32_t rb = sb + RAW_OFF + (uint32_t)((kt & 1) * 16384 + k * 512);
    float4 v[4];
#pragma unroll
    for (int jj = 0; jj < 4; jj++) {
        int c = pg * 4 + jj;
        lds128(v[jj], rb + (uint32_t)((c ^ (k & 7)) << 4));
    }
    uint32_t hb = sb + HALF_OFF + (uint32_t)((kt & 1) * 16384 + k * 256);
#pragma unroll
    for (int g = 0; g < 2; g++) {
        const float4& a = v[2 * g];
        const float4& b = v[2 * g + 1];
        __half h0 = __float2half_rn(a.x), h1 = __float2half_rn(a.y);
        __half h2 = __float2half_rn(a.z), h3 = __float2half_rn(a.w);
        __half h4 = __float2half_rn(b.x), h5 = __float2half_rn(b.y);
        __half h6 = __float2half_rn(b.z), h7 = __float2half_rn(b.w);
        __half l0 = __float2half_rn(a.x - __half2float(h0));
        __half l1 = __float2half_rn(a.y - __half2float(h1));
        __half l2 = __float2half_rn(a.z - __half2float(h2));
        __half l3 = __float2half_rn(a.w - __half2float(h3));
        __half l4 = __float2half_rn(b.x - __half2float(h4));
        __half l5 = __float2half_rn(b.y - __half2float(h5));
        __half l6 = __float2half_rn(b.z - __half2float(h6));
        __half l7 = __float2half_rn(b.w - __half2float(h7));
        __half2 H[4] = {__halves2half2(h0, h1), __halves2half2(h2, h3),
                        __halves2half2(h4, h5), __halves2half2(h6, h7)};
        __half2 L[4] = {__halves2half2(l0, l1), __halves2half2(l2, l3),
                        __halves2half2(l4, l5), __halves2half2(l6, l7)};
        uint32_t hc = (uint32_t)(((pg * 2 + g) ^ (k & 7)) << 4);
        sts128(hb + hc, *(uint32_t*)&H[0], *(uint32_t*)&H[1],
                        *(uint32_t*)&H[2], *(uint32_t*)&H[3]);
        sts128(hb + 8192 + hc, *(uint32_t*)&L[0], *(uint32_t*)&L[1],
                               *(uint32_t*)&L[2], *(uint32_t*)&L[3]);
    }
}

// -------- main GEMM + fused RBF epilogue ---------------------------------------
__global__ __launch_bounds__(256, 2) void duq_mma(const float* __restrict__ feat,
                                                  float* __restrict__ out) {
    extern __shared__ char smem[];
    uint32_t sb = smem_u32(smem);
    int t = threadIdx.x, l = t & 31, w = t >> 5;
    int nb = blockIdx.x, mb = blockIdx.y;
    long P0 = (long)mb * BM;           // 128 | 16384 -> never crosses a batch
    int bb = (int)(P0 >> 14);
    int pinbase = (int)(P0 & 16383);
    int n0 = nb * BN;

    if (t < BN) ((float*)(smem + CENT_OFF))[t] = g_cent[n0 + t];

    int wm = (w >> 1) * 32;            // 4 M-groups of 32
    int wn = (w & 1) * 64;             // 2 N-groups of 64

    int rl  = l & 7;
    int mh  = (l >> 3) & 1;
    int hi  = (l >> 4) & 1;

    float acc[2][8][4];
#pragma unroll
    for (int i = 0; i < 2; i++)
#pragma unroll
        for (int j = 0; j < 8; j++)
#pragma unroll
            for (int q = 0; q < 4; q++) acc[i][j][q] = 0.0f;

    fill_stage(sb, 0, feat, bb, pinbase, n0, t);
    asm volatile("cp.async.commit_group;" ::: "memory");
    fill_stage(sb, 1, feat, bb, pinbase, n0, t);
    asm volatile("cp.async.commit_group;" ::: "memory");
    asm volatile("cp.async.wait_group 1;" ::: "memory");
    __syncthreads();
    convert_tile(sb, 0, t);            // halves(0); visible after loop-top sync

    for (int kt = 0; kt < KTILES; kt++) {
        __syncthreads();               // halves(kt) STS -> ldsm; ring-reuse fence
        if (kt + 2 < KTILES) fill_stage(sb, kt + 2, feat, bb, pinbase, n0, t);
        asm volatile("cp.async.commit_group;" ::: "memory");   // empty group ok
        if (kt + 1 < KTILES) {
            asm volatile("cp.async.wait_group 1;" ::: "memory"); // raw/B(kt+1) done
            convert_tile(sb, kt + 1, t);
        }

        uint32_t Ah = sb + HALF_OFF + (uint32_t)((kt & 1) * 16384);
        uint32_t Bs = sb + B_OFF + (uint32_t)((kt % 3) * 16384);
#pragma unroll
        for (int k16 = 0; k16 < 2; k16++) {
            uint32_t ah[2][4], al[2][4];
#pragma unroll
            for (int mf = 0; mf < 2; mf++) {
                int krow = k16 * 16 + hi * 8 + rl;
                int pcol = wm + mf * 16 + mh * 8;
                uint32_t ad = Ah + (uint32_t)(krow * 256 + (((pcol >> 3) ^ (rl)) << 4));
                ldsm4t(ah[mf], ad);
                ldsm4t(al[mf], ad + 8192);
            }
#pragma unroll
            for (int np = 0; np < 4; np++) {
                int rb = wn + np * 16 + hi * 8 + rl;
                uint32_t off = (uint32_t)(rb * 64 + (((2 * k16 + mh) ^ ((rb >> 1) & 3)) << 4));
                uint32_t bh4[4], bl4[4];
                ldsm4(bh4, Bs + off);
                ldsm4(bl4, Bs + 8192 + off);
#pragma unroll
                for (int mf = 0; mf < 2; mf++)
#pragma unroll
                    for (int h = 0; h < 2; h++)
                        mma_f32(acc[mf][2 * np + h], ah[mf], &bh4[2 * h]);
#pragma unroll
                for (int mf = 0; mf < 2; mf++)
#pragma unroll
                    for (int h = 0; h < 2; h++)
                        mma_f32(acc[mf][2 * np + h], ah[mf], &bl4[2 * h]);
#pragma unroll
                for (int mf = 0; mf < 2; mf++)
#pragma unroll
                    for (int h = 0; h < 2; h++)
                        mma_f32(acc[mf][2 * np + h], al[mf], &bh4[2 * h]);
            }
        }
    }

    // ---- epilogue: diff^2, 16-e reduction (2 quad shuffles), __expf, store ----
    const float* centS = (const float*)(smem + CENT_OFF);
    int q2 = l & 3;
    int cb = (n0 + wn) >> 4;

#pragma unroll
    for (int mf = 0; mf < 2; mf++) {
        float s[4][2];
#pragma unroll
        for (int ch = 0; ch < 4; ch++) { s[ch][0] = 0.0f; s[ch][1] = 0.0f; }
#pragma unroll
        for (int nf = 0; nf < 8; nf++) {
            int ch = nf >> 1;
#pragma unroll
            for (int j = 0; j < 2; j++) {
                float ce = centS[wn + nf * 8 + 2 * q2 + j];
                float d0 = acc[mf][nf][j]     - ce;
                float d1 = acc[mf][nf][2 + j] - ce;
                s[ch][0] = fmaf(d0, d0, s[ch][0]);
                s[ch][1] = fmaf(d1, d1, s[ch][1]);
            }
        }
#pragma unroll
        for (int ch = 0; ch < 4; ch++)
#pragma unroll
            for (int r = 0; r < 2; r++) {
                s[ch][r] += __shfl_xor_sync(0xFFFFFFFFu, s[ch][r], 1);
                s[ch][r] += __shfl_xor_sync(0xFFFFFFFFu, s[ch][r], 2);
            }
        float v0 = (q2 == 0) ? s[0][0] : (q2 == 1) ? s[1][0] : (q2 == 2) ? s[2][0] : s[3][0];
        float v1 = (q2 == 0) ? s[0][1] : (q2 == 1) ? s[1][1] : (q2 == 2) ? s[2][1] : s[3][1];

        long gp = P0 + wm + mf * 16 + (l >> 2);
        int b   = (int)(gp >> 14);
        int pin = (int)(gp & 16383);
        int ch  = cb + q2;
        float* o = out + ((size_t)b * 64 + ch) * 16384 + pin;
        o[0] = __expf(-3.125f * v0);
        o[8] = __expf(-3.125f * v1);
    }
}

// -------- launch ----------------------------------------------------------------
extern "C" void kernel_launch(void* const* d_in, const int* in_sizes, int n_in,
                              void* d_out, int out_size)
{
    const float* feat = (const float*)d_in[0];   // [8, 512, 128, 128]
    const float* wgt  = (const float*)d_in[1];   // [16, 64, 512]
    const float* m    = (const float*)d_in[2];   // [16, 64]
    const float* N    = (const float*)d_in[3];   // [64]
    float* out        = (float*)d_out;           // [8, 64, 128, 128]

    cudaFuncSetAttribute(duq_mma, cudaFuncAttributeMaxDynamicSharedMemorySize, SMEM_TOTAL);

    prep_w<<<1024, 128>>>(wgt, m, N);
    duq_mma<<<dim3(8, 1024), 256, SMEM_TOTAL>>>(feat, out);
}

// round 11
// speedup vs baseline: 1.3443x; 1.3443x over previous
#include <cuda_runtime.h>
#include <cuda_fp16.h>
#include <cstdint>
#include <math.h>

// ============================================================================
// DUQ head via HMMA 3xFP16-split GEMM (R9 base + B-fragment double-buffering).
// out[b,c,p] = exp(-3.125 * sum_e (emb[p, c*16+e] - cent[c*16+e])^2)
// emb = feat[b,:,p].w[n,:], n=c*16+e, K=512.
// a = ah+al, b = bh+bl (exact fp16 splits); acc += ah*bh + ah*bl + al*bh (f32).
// CTA tile 128x128, warp tile 32x64 (8 warps/256 thr), BK=32,
// 3-stage cp.async, 96KB smem, 2 CTAs/SM. B ldsm prefetched one np-group
// ahead so LDS latency is covered by the previous group's 24 MMAs.
// ============================================================================

#define BM 128
#define BN 128
#define BK 32
#define KTILES 16            // 512 / 32
#define STAGE_BYTES 32768    // Ahi 8K | Alo 8K | Bhi 8K | Blo 8K
#define OFF_ALO 8192
#define OFF_BHI 16384
#define OFF_BLO 24576
#define CENT_OFF (3 * STAGE_BYTES)
#define SMEM_TOTAL (CENT_OFF + 512)

// -------- device-global scratch (no cudaMalloc allowed) ----------------------
__device__ __half g_ah[67108864];   // [131072 px][512 k]
__device__ __half g_al[67108864];
__device__ __half g_bh[524288];     // [1024 n][512 k], n = c*16+e
__device__ __half g_bl[524288];
__device__ float  g_cent[1024];

// -------- helpers -------------------------------------------------------------
__device__ __forceinline__ uint32_t smem_u32(const void* p) {
    uint32_t a;
    asm("{ .reg .u64 t; cvta.to.shared.u64 t, %1; cvt.u32.u64 %0, t; }" : "=r"(a) : "l"(p));
    return a;
}
__device__ __forceinline__ void cp16(uint32_t dst, const __half* src) {
    asm volatile("cp.async.cg.shared.global [%0], [%1], 16;"
                 :: "r"(dst), "l"(__cvta_generic_to_global(src)));
}
__device__ __forceinline__ void ldsm4(uint32_t* r, uint32_t addr) {
    asm volatile("ldmatrix.sync.aligned.m8n8.x4.shared.b16 {%0,%1,%2,%3}, [%4];"
                 : "=r"(r[0]), "=r"(r[1]), "=r"(r[2]), "=r"(r[3]) : "r"(addr));
}
__device__ __forceinline__ void mma_f32(float* c, const uint32_t* a, const uint32_t* b) {
    asm volatile("mma.sync.aligned.m16n8k16.row.col.f32.f16.f16.f32 "
                 "{%0,%1,%2,%3}, {%4,%5,%6,%7}, {%8,%9}, {%0,%1,%2,%3};"
                 : "+f"(c[0]), "+f"(c[1]), "+f"(c[2]), "+f"(c[3])
                 : "r"(a[0]), "r"(a[1]), "r"(a[2]), "r"(a[3]), "r"(b[0]), "r"(b[1]));
}

// -------- prep 1: transpose + fp16-split features (half2 coalesced writes) ----
__global__ void prep_feat(const float* __restrict__ feat) {
    __shared__ float tile[32][65];     // [p][k], padded
    int b  = blockIdx.z;
    int p0 = blockIdx.x * 32, k0 = blockIdx.y * 64;
    int tx = threadIdx.x, ty = threadIdx.y;                // (32, 8)
    const float* src = feat + ((size_t)b * 512 + k0) * 16384 + p0;
#pragma unroll
    for (int i = 0; i < 8; i++) {
        int kr = ty + 8 * i;
        tile[tx][kr] = src[(size_t)kr * 16384 + tx];
    }
    __syncthreads();
    size_t dbase = ((size_t)b * 16384 + p0) * 512 + k0;
#pragma unroll
    for (int j = 0; j < 4; j++) {
        int pr = ty + 8 * j;
        float v0 = tile[pr][2 * tx];
        float v1 = tile[pr][2 * tx + 1];
        __half h0 = __float2half_rn(v0);
        __half h1 = __float2half_rn(v1);
        __half l0 = __float2half_rn(v0 - __half2float(h0));
        __half l1 = __float2half_rn(v1 - __half2float(h1));
        size_t off = dbase + (size_t)pr * 512 + 2 * tx;
        *(__half2*)(g_ah + off) = __halves2half2(h0, h1);
        *(__half2*)(g_al + off) = __halves2half2(l0, l1);
    }
}

// -------- prep 2: weights reorder + split, centroids --------------------------
__global__ void prep_w(const float* __restrict__ wgt, const float* __restrict__ m,
                       const float* __restrict__ Nb) {
    int n = blockIdx.x;                 // n = c*16 + e
    int c = n >> 4, e = n & 15;
    const float* src = wgt + ((size_t)e * 64 + c) * 512;
    for (int k = threadIdx.x; k < 512; k += 128) {
        float v = src[k];
        __half hi = __float2half_rn(v);
        g_bh[(size_t)n * 512 + k] = hi;
        g_bl[(size_t)n * 512 + k] = __float2half_rn(v - __half2float(hi));
    }
    if (threadIdx.x == 0) g_cent[n] = m[e * 64 + c] / Nb[c];
}

// -------- stage fill (256 threads): 8 x 16B cp.async per thread ----------------
// 64B rows (4 chunks of 16B), swizzle chunk ^ ((row>>1)&3) -> ldsm conflict-free
__device__ __forceinline__ void fill_stage(uint32_t sb, int s, int kt, long P0, int n0, int t) {
    int kb = kt * BK;
    uint32_t st = sb + s * STAGE_BYTES;
    int r = t >> 2, c = t & 3;
#pragma unroll
    for (int i = 0; i < 2; i++) {
        int rr = r + i * 64;
        uint32_t d = st + rr * 64 + (uint32_t)((c ^ ((rr >> 1) & 3)) << 4);
        size_t asrc = (size_t)(P0 + rr) * 512 + kb + c * 8;
        size_t bsrc = (size_t)(n0 + rr) * 512 + kb + c * 8;
        cp16(d,           g_ah + asrc);
        cp16(d + OFF_ALO, g_al + asrc);
        cp16(d + OFF_BHI, g_bh + bsrc);
        cp16(d + OFF_BLO, g_bl + bsrc);
    }
}

// -------- main GEMM + fused RBF epilogue ---------------------------------------
__global__ __launch_bounds__(256, 2) void duq_mma(float* __restrict__ out) {
    extern __shared__ char smem[];
    uint32_t sb = smem_u32(smem);
    int t = threadIdx.x, l = t & 31, w = t >> 5;
    int nb = blockIdx.x, mb = blockIdx.y;
    long P0 = (long)mb * BM;           // 128 | 16384 -> never crosses a batch
    int n0 = nb * BN;

    if (t < BN) ((float*)(smem + CENT_OFF))[t] = g_cent[n0 + t];

    int wm = (w >> 1) * 32;            // 4 M-groups of 32
    int wn = (w & 1) * 64;             // 2 N-groups of 64

    int rl  = l & 7;                   // row within 8-row matrix
    int mh  = (l >> 3) & 1;            // matrix half bit
    int hi  = (l >> 4) & 1;            // k-chunk bit

    float acc[2][8][4];
#pragma unroll
    for (int i = 0; i < 2; i++)
#pragma unroll
        for (int j = 0; j < 8; j++)
#pragma unroll
            for (int q = 0; q < 4; q++) acc[i][j][q] = 0.0f;

    fill_stage(sb, 0, 0, P0, n0, t);
    asm volatile("cp.async.commit_group;" ::: "memory");
    fill_stage(sb, 1, 1, P0, n0, t);
    asm volatile("cp.async.commit_group;" ::: "memory");

    for (int kt = 0; kt < KTILES; kt++) {
        asm volatile("cp.async.wait_group 1;" ::: "memory");
        __syncthreads();

        if (kt + 2 < KTILES) fill_stage(sb, (kt + 2) % 3, kt + 2, P0, n0, t);
        asm volatile("cp.async.commit_group;" ::: "memory");

        uint32_t As = sb + (kt % 3) * STAGE_BYTES;
#pragma unroll
        for (int k16 = 0; k16 < 2; k16++) {
            uint32_t ah[2][4], al[2][4];
#pragma unroll
            for (int mf = 0; mf < 2; mf++) {
                int ra = wm + mf * 16 + mh * 8 + rl;
                uint32_t off = (uint32_t)(ra * 64 + (((2 * k16 + hi) ^ ((ra >> 1) & 3)) << 4));
                ldsm4(ah[mf], As + off);
                ldsm4(al[mf], As + OFF_ALO + off);
            }
            // B double buffer: prefetch np+1 before issuing MMAs of np.
            uint32_t bh4[2][4], bl4[2][4];
            {
                int rb = wn + 0 * 16 + hi * 8 + rl;
                uint32_t off = (uint32_t)(rb * 64 + (((2 * k16 + mh) ^ ((rb >> 1) & 3)) << 4));
                ldsm4(bh4[0], As + OFF_BHI + off);
                ldsm4(bl4[0], As + OFF_BLO + off);
            }
#pragma unroll
            for (int np = 0; np < 4; np++) {
                int cur = np & 1, nxt = cur ^ 1;
                if (np < 3) {
                    int rb = wn + (np + 1) * 16 + hi * 8 + rl;
                    uint32_t off = (uint32_t)(rb * 64 + (((2 * k16 + mh) ^ ((rb >> 1) & 3)) << 4));
                    ldsm4(bh4[nxt], As + OFF_BHI + off);
                    ldsm4(bl4[nxt], As + OFF_BLO + off);
                }
                // product-major order (acc RAW distance 4)
#pragma unroll
                for (int mf = 0; mf < 2; mf++)
#pragma unroll
                    for (int h = 0; h < 2; h++)
                        mma_f32(acc[mf][2 * np + h], ah[mf], &bh4[cur][2 * h]);
#pragma unroll
                for (int mf = 0; mf < 2; mf++)
#pragma unroll
                    for (int h = 0; h < 2; h++)
                        mma_f32(acc[mf][2 * np + h], ah[mf], &bl4[cur][2 * h]);
#pragma unroll
                for (int mf = 0; mf < 2; mf++)
#pragma unroll
                    for (int h = 0; h < 2; h++)
                        mma_f32(acc[mf][2 * np + h], al[mf], &bh4[cur][2 * h]);
            }
        }
    }

    // ---- epilogue: diff^2, 16-e reduction (2 quad shuffles), __expf, store ----
    const float* centS = (const float*)(smem + CENT_OFF);
    int q2 = l & 3;
    int cb = (n0 + wn) >> 4;           // first of this warp's 4 channels

#pragma unroll
    for (int mf = 0; mf < 2; mf++) {
        float s[4][2];
#pragma unroll
        for (int ch = 0; ch < 4; ch++) { s[ch][0] = 0.0f; s[ch][1] = 0.0f; }
#pragma unroll
        for (int nf = 0; nf < 8; nf++) {
            int ch = nf >> 1;
#pragma unroll
            for (int j = 0; j < 2; j++) {
                float ce = centS[wn + nf * 8 + 2 * q2 + j];
                float d0 = acc[mf][nf][j]     - ce;
                float d1 = acc[mf][nf][2 + j] - ce;
                s[ch][0] = fmaf(d0, d0, s[ch][0]);
                s[ch][1] = fmaf(d1, d1, s[ch][1]);
            }
        }
#pragma unroll
        for (int ch = 0; ch < 4; ch++)
#pragma unroll
            for (int r = 0; r < 2; r++) {
                s[ch][r] += __shfl_xor_sync(0xFFFFFFFFu, s[ch][r], 1);
                s[ch][r] += __shfl_xor_sync(0xFFFFFFFFu, s[ch][r], 2);
            }
        float v0 = (q2 == 0) ? s[0][0] : (q2 == 1) ? s[1][0] : (q2 == 2) ? s[2][0] : s[3][0];
        float v1 = (q2 == 0) ? s[0][1] : (q2 == 1) ? s[1][1] : (q2 == 2) ? s[2][1] : s[3][1];

        long gp = P0 + wm + mf * 16 + (l >> 2);
        int b   = (int)(gp >> 14);
        int pin = (int)(gp & 16383);
        int ch  = cb + q2;
        float* o = out + ((size_t)b * 64 + ch) * 16384 + pin;
        o[0] = __expf(-3.125f * v0);
        o[8] = __expf(-3.125f * v1);
    }
}

// -------- launch ----------------------------------------------------------------
extern "C" void kernel_launch(void* const* d_in, const int* in_sizes, int n_in,
                              void* d_out, int out_size)
{
    const float* feat = (const float*)d_in[0];   // [8, 512, 128, 128]
    const float* wgt  = (const float*)d_in[1];   // [16, 64, 512]
    const float* m    = (const float*)d_in[2];   // [16, 64]
    const float* N    = (const float*)d_in[3];   // [64]
    float* out        = (float*)d_out;           // [8, 64, 128, 128]

    cudaFuncSetAttribute(duq_mma, cudaFuncAttributeMaxDynamicSharedMemorySize, SMEM_TOTAL);

    prep_feat<<<dim3(512, 8, 8), dim3(32, 8)>>>(feat);
    prep_w<<<1024, 128>>>(wgt, m, N);
    duq_mma<<<dim3(8, 1024), 256, SMEM_TOTAL>>>(out);
}